// round 9
// baseline (speedup 1.0000x reference)
#include <cuda_runtime.h>
#include <math.h>
#include <stdint.h>

// BuildingModule: 3-state RC thermal scan, B=8192 chains x 1023 serial steps.
// 64-thread blocks = 2 fully independent compute warps (32 chains each) on
// SMSP0/SMSP1. All gmem<->smem traffic via bulk-async (UBLKCP) engine copies:
//   u:   per-lane 512B cp.async.bulk loads, mbarrier complete_tx (2-deep)
//   out: per-lane 192B cp.async.bulk stores, bulk_group (ob double-buffered)
// Math: incremental reciprocal (cubic poly for 2^-m), kl-prefolded coeffs.

#define BATCH   8192
#define TSTEPS  1024
#define CHUNK   16
#define NCHUNK  (TSTEPS / CHUNK)        // 64
#define ROWW    132                     // words: 128 data + 4 pad (528B, 16B-aligned)
#define OROWW   52                      // words: 48 data + 4 pad (208B, 16B-aligned)
#define USTRIDE (TSTEPS * 8)            // floats per chain in u
#define OSTRIDE (TSTEPS * 3)            // floats per chain in out

#define UBUF_WORDS (32 * ROWW)          // one u stage buffer   (16896 B)
#define OBUF_WORDS (32 * OROWW)         // one out stage buffer ( 6656 B)
#define WARP_WORDS (2 * UBUF_WORDS + 2 * OBUF_WORDS)
#define SMEM_BYTES (2 * WARP_WORDS * 4 + 64)   // + mbarriers

__device__ __forceinline__ float rcpa(float x) {
    float y; asm("rcp.approx.ftz.f32 %0, %1;" : "=f"(y) : "f"(x)); return y;
}
__device__ __forceinline__ float ex2a(float x) {
    float y; asm("ex2.approx.ftz.f32 %0, %1;" : "=f"(y) : "f"(x)); return y;
}
__device__ __forceinline__ void mbar_init(uint32_t a, uint32_t cnt) {
    asm volatile("mbarrier.init.shared.b64 [%0], %1;" :: "r"(a), "r"(cnt) : "memory");
}
__device__ __forceinline__ void mbar_arrive_expect(uint32_t a, uint32_t tx) {
    asm volatile("mbarrier.arrive.expect_tx.shared.b64 _, [%0], %1;"
                 :: "r"(a), "r"(tx) : "memory");
}
__device__ __forceinline__ void mbar_wait(uint32_t a, uint32_t parity) {
    asm volatile(
        "{\n\t"
        ".reg .pred P;\n\t"
        "WL_%=:\n\t"
        "mbarrier.try_wait.parity.acquire.cta.shared::cta.b64 P, [%0], %1, 0x989680;\n\t"
        "@P bra.uni WD_%=;\n\t"
        "bra.uni WL_%=;\n\t"
        "WD_%=:\n\t"
        "}" :: "r"(a), "r"(parity) : "memory");
}
__device__ __forceinline__ void bulk_ld(uint32_t sdst, const float* gsrc,
                                        uint32_t bytes, uint32_t mbar) {
    asm volatile("cp.async.bulk.shared::cta.global.mbarrier::complete_tx::bytes "
                 "[%0], [%1], %2, [%3];"
                 :: "r"(sdst), "l"(gsrc), "r"(bytes), "r"(mbar) : "memory");
}
__device__ __forceinline__ void bulk_st(float* gdst, uint32_t ssrc, uint32_t bytes) {
    asm volatile("cp.async.bulk.global.shared::cta.bulk_group [%0], [%1], %2;"
                 :: "l"(gdst), "r"(ssrc), "r"(bytes) : "memory");
}
__device__ __forceinline__ void bulk_commit() {
    asm volatile("cp.async.bulk.commit_group;" ::: "memory");
}
__device__ __forceinline__ void bulk_wait_read1() {
    asm volatile("cp.async.bulk.wait_group.read 1;" ::: "memory");
}
__device__ __forceinline__ void bulk_wait0() {
    asm volatile("cp.async.bulk.wait_group 0;" ::: "memory");
}
__device__ __forceinline__ void fence_async() {
    asm volatile("fence.proxy.async.shared::cta;" ::: "memory");
}

extern __shared__ float smem[];

__global__ void __launch_bounds__(64)
bm_kernel(const float* __restrict__ x0g,
          const float* __restrict__ ug,
          const float* __restrict__ lamg,
          float* __restrict__ outg)
{
    const int tid  = threadIdx.x;
    const int lane = tid & 31;
    const int wid  = tid >> 5;                 // 0 or 1 -> SMSP 0 / 1
    const int b0   = blockIdx.x * 64 + wid * 32;
    const int b    = b0 + lane;

    float* ub = smem + wid * WARP_WORDS;       // [2][32*ROWW]
    float* ob = ub + 2 * UBUF_WORDS;           // [2][32*OROWW]
    // mbarriers at tail: [wid][bi]
    uint32_t mbar0 = (uint32_t)__cvta_generic_to_shared(smem + 2 * WARP_WORDS)
                     + wid * 16;

    const float e12 = expf(lamg[0]);
    const float e23 = expf(lamg[1]);
    const float ee0 = expf(lamg[2]),  ee1 = expf(lamg[3]),  ee2 = expf(lamg[4]);
    const float es0 = expf(lamg[5]),  es1 = expf(lamg[6]),  es2 = expf(lamg[7]);
    const float eh0 = expf(lamg[8]),  eh1 = expf(lamg[9]),  eh2 = expf(lamg[10]);
    const float ec0 = expf(lamg[11]), ec1 = expf(lamg[12]), ec2 = expf(lamg[13]);

    const float kl0 = (float)(60.0 / 10665991.0 * 1.4426950408889634);
    const float kl1 = (float)(60.0 / 27000000.0 * 1.4426950408889634);
    const float kl2 = (float)(60.0 /  7953253.0 * 1.4426950408889634);

    const float g12_0  =  kl0 * e12;
    const float ng12_1 = -kl1 * e12;
    const float g23_1  =  kl1 * e23;
    const float ng23_2 = -kl2 * e23;
    const float eeK0 = kl0*ee0, eeK1 = kl1*ee1, eeK2 = kl2*ee2;
    const float neeK0 = -eeK0, neeK1 = -eeK1, neeK2 = -eeK2;
    const float esK0 = kl0*es0, esK1 = kl1*es1, esK2 = kl2*es2;
    const float ehK0 = kl0*eh0, ehK1 = kl1*eh1, ehK2 = kl2*eh2;
    const float ecK0 = kl0*ec0, ecK1 = kl1*ec1, ecK2 = kl2*ec2;

    float x0 = x0g[b * 3 + 0];
    float x1 = x0g[b * 3 + 1];
    float x2 = x0g[b * 3 + 2];
    float i0 = rcpa(x0), i1 = rcpa(x1), i2 = rcpa(x2);
    i0 = i0 * (2.0f - x0 * i0);
    i1 = i1 * (2.0f - x1 * i1);
    i2 = i2 * (2.0f - x2 * i2);

    // per-lane addresses for bulk traffic (each lane owns chain b = b0+lane)
    const float* usrc = ug + (size_t)b * USTRIDE;        // + c*128 floats
    float*       gdst = outg + (size_t)b * OSTRIDE;      // + c*48 floats
    const uint32_t ubA = (uint32_t)__cvta_generic_to_shared(ub) + lane * (ROWW * 4);
    const uint32_t obA = (uint32_t)__cvta_generic_to_shared(ob) + lane * (OROWW * 4);

    // init mbarriers (count = 32: every lane arrives with expect_tx per stage)
    if (lane == 0) {
        mbar_init(mbar0 + 0, 32);
        mbar_init(mbar0 + 8, 32);
    }
    __syncwarp();

    // prime 2-deep u pipeline: chunk 0 -> buf0, chunk 1 -> buf1
    mbar_arrive_expect(mbar0 + 0, 512);
    bulk_ld(ubA,                  usrc,                 512, mbar0 + 0);
    mbar_arrive_expect(mbar0 + 8, 512);
    bulk_ld(ubA + UBUF_WORDS * 4, usrc + (CHUNK * 8),   512, mbar0 + 8);

    for (int c = 0; c < NCHUNK; c++) {
        const int bi = c & 1;

        // wait for chunk c resident in ub[bi]; parity = stage index (c>>1) & 1
        mbar_wait(mbar0 + bi * 8, (c >> 1) & 1);

        const float* row = &ub[bi * UBUF_WORDS + lane * ROWW];
        float* orow = &ob[bi * OBUF_WORDS + lane * OROWW];

        float4 ua = *(const float4*)(row);        // u0,u1,h0,h1
        float4 uc = *(const float4*)(row + 4);    // h2,c0,c1,c2

#pragma unroll
        for (int j = 0; j < CHUNK; j++) {
            float4 na, nc;
            if (j < CHUNK - 1) {
                na = *(const float4*)(row + (j + 1) * 8);
                nc = *(const float4*)(row + (j + 1) * 8 + 4);
            }

            // out row 16c+j <- current state, masked by u0 of this row
            {
                const bool nm = (c == 0) && (j == 0);
                const bool mv = !nm && (ua.x < 1e-6f);
                orow[j * 3 + 0] = mv ? -1.0f : x0;
                orow[j * 3 + 1] = mv ? -1.0f : x1;
                orow[j * 3 + 2] = mv ? -1.0f : x2;
            }

            // scan step consuming this u row
            const float u0 = ua.x, u1 = ua.y;
            const float d12 = i0 - i1;
            const float d23 = i1 - i2;
            const float w0 = fmaf(esK0, u1, fmaf(ehK0, ua.z, fmaf(ecK0, uc.y, neeK0)));
            const float w1 = fmaf(esK1, u1, fmaf(ehK1, ua.w, fmaf(ecK1, uc.z, neeK1)));
            const float w2 = fmaf(esK2, u1, fmaf(ehK2, uc.x, fmaf(ecK2, uc.w, neeK2)));
            const float q0 = fmaf(eeK0, i0 * u0, w0);
            const float q1 = fmaf(eeK1, i1 * u0, w1);
            const float q2 = fmaf(eeK2, i2 * u0, w2);
            const float m0 = fmaf(g12_0  * d12, x1, q0);
            const float m1 = fmaf(g23_1  * d23, x2, fmaf(ng12_1 * d12, x0, q1));
            const float m2 = fmaf(ng23_2 * d23, x1, q2);
            const float r0 = fmaf(fmaf(fmaf(-0.05550410866f, m0, 0.24022650696f), m0, -0.69314718056f), m0, 1.0f);
            const float r1 = fmaf(fmaf(fmaf(-0.05550410866f, m1, 0.24022650696f), m1, -0.69314718056f), m1, 1.0f);
            const float r2 = fmaf(fmaf(fmaf(-0.05550410866f, m2, 0.24022650696f), m2, -0.69314718056f), m2, 1.0f);
            x0 *= ex2a(m0);  x1 *= ex2a(m1);  x2 *= ex2a(m2);
            i0 *= r0;        i1 *= r1;        i2 *= r2;

            ua = na; uc = nc;
        }

        // order generic STS (ob) and generic LDS (ub) before async-proxy ops
        fence_async();

        // drain ob[bi]: each lane bulk-stores its own 192B row (engine copy)
        bulk_st(gdst + (size_t)c * (CHUNK * 3), obA + bi * (OBUF_WORDS * 4), 192);
        bulk_commit();

        // stage chunk c+2 into ub[bi] (just consumed)
        if (c + 2 < NCHUNK) {
            mbar_arrive_expect(mbar0 + bi * 8, 512);
            bulk_ld(ubA + bi * (UBUF_WORDS * 4),
                    usrc + (size_t)(c + 2) * (CHUNK * 8), 512, mbar0 + bi * 8);
        }

        // allow <=1 outstanding store group: G(c-1) done -> ob[(c+1)&1] free
        bulk_wait_read1();
    }

    bulk_wait0();   // flush final store groups before exit
}

extern "C" void kernel_launch(void* const* d_in, const int* in_sizes, int n_in,
                              void* d_out, int out_size)
{
    const float* x0  = nullptr;
    const float* u   = nullptr;
    const float* lam = nullptr;
    for (int i = 0; i < n_in; i++) {
        if (in_sizes[i] == 14)               lam = (const float*)d_in[i];
        else if (in_sizes[i] == BATCH * 3)   x0  = (const float*)d_in[i];
        else                                 u   = (const float*)d_in[i];
    }
    cudaFuncSetAttribute(bm_kernel,
                         cudaFuncAttributeMaxDynamicSharedMemorySize,
                         SMEM_BYTES);
    bm_kernel<<<BATCH / 64, 64, SMEM_BYTES>>>(x0, u, lam, (float*)d_out);
}

// round 10
// speedup vs baseline: 2.1003x; 2.1003x over previous
#include <cuda_runtime.h>
#include <math.h>
#include <stdint.h>

// BuildingModule: 3-state RC thermal scan, B=8192 chains x 1023 serial steps.
// 64-thread blocks = 2 independent compute+IO warps (32 chains each) on
// SMSP0/SMSP1. All IO interleaved into the compute loop:
//   - u: 3-deep smem ring, 2 cp.async per step (stage chunk c+2 while
//        computing chunk c)
//   - out: 4-step register buffering -> conflict-free STS.128; drain of
//        chunk c-1 (12x LDS.128+STG.128) spread across chunk c's steps
// Math: incremental reciprocal (cubic poly for 2^-m), kl-prefolded coeffs.

#define BATCH   8192
#define TSTEPS  1024
#define CHUNK   16
#define NCHUNK  (TSTEPS / CHUNK)        // 64
#define ROWW    132                     // words: 128 data + 4 pad
#define OROWW   52                      // words: 48 data + 4 pad
#define USTRIDE (TSTEPS * 8)            // floats per chain in u
#define OSTRIDE (TSTEPS * 3)            // floats per chain in out

#define UBUF_WORDS (32 * ROWW)          // one u ring slot   (16896 B)
#define OBUF_WORDS (32 * OROWW)         // one out buffer    ( 6656 B)
#define WARP_WORDS (3 * UBUF_WORDS + 2 * OBUF_WORDS)
#define SMEM_BYTES (2 * WARP_WORDS * 4) // 127744 B per block

__device__ __forceinline__ void cpa16(uint32_t s, const float* g) {
    asm volatile("cp.async.cg.shared.global [%0], [%1], 16;" :: "r"(s), "l"(g));
}
__device__ __forceinline__ void cpa_commit() {
    asm volatile("cp.async.commit_group;" ::: "memory");
}
__device__ __forceinline__ void cpa_wait1() {
    asm volatile("cp.async.wait_group 1;" ::: "memory");
}
__device__ __forceinline__ float rcpa(float x) {
    float y; asm("rcp.approx.ftz.f32 %0, %1;" : "=f"(y) : "f"(x)); return y;
}
__device__ __forceinline__ float ex2a(float x) {
    float y; asm("ex2.approx.ftz.f32 %0, %1;" : "=f"(y) : "f"(x)); return y;
}

extern __shared__ float smem[];

__global__ void __launch_bounds__(64)
bm_kernel(const float* __restrict__ x0g,
          const float* __restrict__ ug,
          const float* __restrict__ lamg,
          float* __restrict__ outg)
{
    const int tid  = threadIdx.x;
    const int lane = tid & 31;
    const int wid  = tid >> 5;                 // 0 or 1 -> SMSP 0 / 1
    const int b0   = blockIdx.x * 64 + wid * 32;
    const int b    = b0 + lane;

    float* ub = smem + wid * WARP_WORDS;       // [3][32*ROWW] ring
    float* ob = ub + 3 * UBUF_WORDS;           // [2][32*OROWW]
    const uint32_t ubS = (uint32_t)__cvta_generic_to_shared(ub);

    const float e12 = expf(lamg[0]);
    const float e23 = expf(lamg[1]);
    const float ee0 = expf(lamg[2]),  ee1 = expf(lamg[3]),  ee2 = expf(lamg[4]);
    const float es0 = expf(lamg[5]),  es1 = expf(lamg[6]),  es2 = expf(lamg[7]);
    const float eh0 = expf(lamg[8]),  eh1 = expf(lamg[9]),  eh2 = expf(lamg[10]);
    const float ec0 = expf(lamg[11]), ec1 = expf(lamg[12]), ec2 = expf(lamg[13]);

    const float kl0 = (float)(60.0 / 10665991.0 * 1.4426950408889634);
    const float kl1 = (float)(60.0 / 27000000.0 * 1.4426950408889634);
    const float kl2 = (float)(60.0 /  7953253.0 * 1.4426950408889634);

    const float g12_0  =  kl0 * e12;
    const float ng12_1 = -kl1 * e12;
    const float g23_1  =  kl1 * e23;
    const float ng23_2 = -kl2 * e23;
    const float eeK0 = kl0*ee0, eeK1 = kl1*ee1, eeK2 = kl2*ee2;
    const float neeK0 = -eeK0, neeK1 = -eeK1, neeK2 = -eeK2;
    const float esK0 = kl0*es0, esK1 = kl1*es1, esK2 = kl2*es2;
    const float ehK0 = kl0*eh0, ehK1 = kl1*eh1, ehK2 = kl2*eh2;
    const float ecK0 = kl0*ec0, ecK1 = kl1*ec1, ecK2 = kl2*ec2;

    float x0 = x0g[b * 3 + 0];
    float x1 = x0g[b * 3 + 1];
    float x2 = x0g[b * 3 + 2];
    float i0 = rcpa(x0), i1 = rcpa(x1), i2 = rcpa(x2);
    i0 = i0 * (2.0f - x0 * i0);
    i1 = i1 * (2.0f - x1 * i1);
    i2 = i2 * (2.0f - x2 * i2);

    const float* up0 = ug + (size_t)b0 * USTRIDE;   // warp's chain-0 u base

    // Serialized staging for priming only.
#define STAGE_FULL(C, SLOT) do {                                              \
    uint32_t s = ubS + (SLOT) * (UBUF_WORDS * 4) + lane * 16;                 \
    const float* g = up0 + (size_t)(C) * (CHUNK * 8) + lane * 4;              \
    _Pragma("unroll")                                                         \
    for (int i_ = 0; i_ < 32; i_++) {                                         \
        cpa16(s, g);                                                          \
        s += ROWW * 4;                                                        \
        g += USTRIDE;                                                         \
    }                                                                         \
    cpa_commit();                                                             \
} while (0)

    STAGE_FULL(0, 0);
    STAGE_FULL(1, 1);
    cpa_wait1();               // chunk 0 resident
    __syncwarp();

    int rd = 0;                // ring slot holding chunk c
    for (int c = 0; c < NCHUNK; c++) {
        const int bo  = c & 1;               // ob buffer for this chunk
        const int wrs = (rd + 2 >= 3) ? rd - 1 : rd + 2;  // slot for chunk c+2
        const bool stage_on = (c + 2 < NCHUNK);
        const bool drain_on = (c > 0);

        const float*  row   = &ub[rd * UBUF_WORDS + lane * ROWW];
        float*        orow  = &ob[bo * OBUF_WORDS + lane * OROWW];
        const float*  obpre = &ob[(bo ^ 1) * OBUF_WORDS];
        const uint32_t ubN  = ubS + wrs * (UBUF_WORDS * 4) + lane * 16;
        const float*  usN   = up0 + (size_t)(c + 2) * (CHUNK * 8) + lane * 4;
        float*        gpre  = outg + (size_t)(c - 1) * (CHUNK * 3);  // + chain*OSTRIDE

        float sb[12];          // 4 steps x 3 comps, masked, reg-resident

        float4 ua = *(const float4*)(row);        // u0,u1,h0,h1
        float4 uc = *(const float4*)(row + 4);    // h2,c0,c1,c2

#pragma unroll
        for (int j = 0; j < CHUNK; j++) {
            // stage 2 chain-rows of chunk c+2 (engine-paced, off-chain)
            if (stage_on) {
                cpa16(ubN + (2*j)     * (ROWW * 4), usN + (size_t)(2*j)     * USTRIDE);
                cpa16(ubN + (2*j + 1) * (ROWW * 4), usN + (size_t)(2*j + 1) * USTRIDE);
            }
            // drain one coalesced 16B unit of chunk c-1 per step (12 of 16)
            if (drain_on && j < 12) {
                const int unit  = j * 32 + lane;
                const int chain = unit / 12;
                const int o     = unit - chain * 12;
                const float4 v = *(const float4*)(obpre + chain * OROWW + o * 4);
                *(float4*)(gpre + (size_t)(b0 + chain) * OSTRIDE + o * 4) = v;
            }

            float4 na, nc;
            if (j < CHUNK - 1) {
                na = *(const float4*)(row + (j + 1) * 8);
                nc = *(const float4*)(row + (j + 1) * 8 + 4);
            }

            // out row 16c+j <- current state, masked by u0 of this row
            {
                const bool nm = (c == 0) && (j == 0);
                const bool mv = !nm && (ua.x < 1e-6f);
                const int  s  = (j & 3) * 3;
                sb[s + 0] = mv ? -1.0f : x0;
                sb[s + 1] = mv ? -1.0f : x1;
                sb[s + 2] = mv ? -1.0f : x2;
            }

            // scan step consuming this u row
            const float u0 = ua.x, u1 = ua.y;
            const float d12 = i0 - i1;
            const float d23 = i1 - i2;
            const float w0 = fmaf(esK0, u1, fmaf(ehK0, ua.z, fmaf(ecK0, uc.y, neeK0)));
            const float w1 = fmaf(esK1, u1, fmaf(ehK1, ua.w, fmaf(ecK1, uc.z, neeK1)));
            const float w2 = fmaf(esK2, u1, fmaf(ehK2, uc.x, fmaf(ecK2, uc.w, neeK2)));
            const float q0 = fmaf(eeK0, i0 * u0, w0);
            const float q1 = fmaf(eeK1, i1 * u0, w1);
            const float q2 = fmaf(eeK2, i2 * u0, w2);
            const float m0 = fmaf(g12_0  * d12, x1, q0);
            const float m1 = fmaf(g23_1  * d23, x2, fmaf(ng12_1 * d12, x0, q1));
            const float m2 = fmaf(ng23_2 * d23, x1, q2);
            const float r0 = fmaf(fmaf(fmaf(-0.05550410866f, m0, 0.24022650696f), m0, -0.69314718056f), m0, 1.0f);
            const float r1 = fmaf(fmaf(fmaf(-0.05550410866f, m1, 0.24022650696f), m1, -0.69314718056f), m1, 1.0f);
            const float r2 = fmaf(fmaf(fmaf(-0.05550410866f, m2, 0.24022650696f), m2, -0.69314718056f), m2, 1.0f);
            x0 *= ex2a(m0);  x1 *= ex2a(m1);  x2 *= ex2a(m2);
            i0 *= r0;        i1 *= r1;        i2 *= r2;

            ua = na; uc = nc;

            // flush 4 buffered steps: 3x STS.128, conflict-free at stride 52
            if ((j & 3) == 3) {
                float* dst = orow + (j - 3) * 3;
                *(float4*)(dst + 0) = make_float4(sb[0], sb[1], sb[2],  sb[3]);
                *(float4*)(dst + 4) = make_float4(sb[4], sb[5], sb[6],  sb[7]);
                *(float4*)(dst + 8) = make_float4(sb[8], sb[9], sb[10], sb[11]);
            }
        }

        cpa_commit();          // close group for chunk c+2 (possibly empty)
        cpa_wait1();           // chunk c+1 resident (c+2 may still fly)
        __syncwarp();          // ob[bo] visible for next chunk's cross-lane drain

        rd = (rd + 1 >= 3) ? 0 : rd + 1;
    }

    // drain the final chunk (NCHUNK-1, ob buffer 1) synchronously
    {
        const float* obl = &ob[1 * OBUF_WORDS];
        float* gl = outg + (size_t)(NCHUNK - 1) * (CHUNK * 3);
#pragma unroll
        for (int it = 0; it < 12; it++) {
            const int unit  = it * 32 + lane;
            const int chain = unit / 12;
            const int o     = unit - chain * 12;
            const float4 v = *(const float4*)(obl + chain * OROWW + o * 4);
            *(float4*)(gl + (size_t)(b0 + chain) * OSTRIDE + o * 4) = v;
        }
    }
}

extern "C" void kernel_launch(void* const* d_in, const int* in_sizes, int n_in,
                              void* d_out, int out_size)
{
    const float* x0  = nullptr;
    const float* u   = nullptr;
    const float* lam = nullptr;
    for (int i = 0; i < n_in; i++) {
        if (in_sizes[i] == 14)               lam = (const float*)d_in[i];
        else if (in_sizes[i] == BATCH * 3)   x0  = (const float*)d_in[i];
        else                                 u   = (const float*)d_in[i];
    }
    cudaFuncSetAttribute(bm_kernel,
                         cudaFuncAttributeMaxDynamicSharedMemorySize,
                         SMEM_BYTES);
    bm_kernel<<<BATCH / 64, 64, SMEM_BYTES>>>(x0, u, lam, (float*)d_out);
}